// round 13
// baseline (speedup 1.0000x reference)
#include <cuda_runtime.h>
#include <cuda_bf16.h>

// ExpmLogm on symmetric 3x3 per-voxel matrices collapses to the identity:
//   eigh(M) -> (S,U); log(exp(S)) = S; U diag(S) U^T = M  (== input).
// Optimal = streaming D2D copy of ~302 MB (irreducible read+write).
//
// TERMINAL CONFIGURATION — full sweep resolved (kernel time, ncu):
//   copy path : SM kernel > driver memcpy engine
//   VPT       : 1 (42.5us) | 4 (39.9-41.3us, WIN) | 8 (42.7us, occ loss)
//   TPB       : 256 (WIN) | 512 (43.9us, L1tex queue contention)
//   predicates: exact-fit (no bounds checks) > guarded
// Winner: ~7.5 TB/s wall vs 37.7us physical floor @ 8 TB/s spec. dur_us
// spread (48.8-51.2 on identical binaries) is harness-overhead noise;
// re-sampling the best config is the only remaining move.

#define VPT 4          // float4 per thread
#define TPB 256        // threads per block

// Exact-fit path: grid*TPB*VPT == n4, no predicates, front-batched loads.
__global__ __launch_bounds__(TPB) void expmlogm_copy_exact(
    const float4* __restrict__ in, float4* __restrict__ out) {
    int base = blockIdx.x * (TPB * VPT) + threadIdx.x;
    float4 v[VPT];
    #pragma unroll
    for (int k = 0; k < VPT; k++) v[k] = __ldcs(&in[base + k * TPB]);
    #pragma unroll
    for (int k = 0; k < VPT; k++) __stcs(&out[base + k * TPB], v[k]);
}

// Generic predicated path (fallback for non-divisible sizes; unused here).
__global__ __launch_bounds__(TPB) void expmlogm_copy_kernel(
    const float4* __restrict__ in, float4* __restrict__ out, int n4) {
    int base = blockIdx.x * (TPB * VPT) + threadIdx.x;
    float4 v[VPT];
    int idx[VPT];
    #pragma unroll
    for (int k = 0; k < VPT; k++) {
        idx[k] = base + k * TPB;
        if (idx[k] < n4) v[k] = __ldcs(&in[idx[k]]);
    }
    #pragma unroll
    for (int k = 0; k < VPT; k++) {
        if (idx[k] < n4) __stcs(&out[idx[k]], v[k]);
    }
}

__global__ void expmlogm_copy_tail(const float* __restrict__ in,
                                   float* __restrict__ out,
                                   int start, int n) {
    int i = start + blockIdx.x * blockDim.x + threadIdx.x;
    if (i < n) out[i] = in[i];
}

extern "C" void kernel_launch(void* const* d_in, const int* in_sizes, int n_in,
                              void* d_out, int out_size) {
    const float* x = (const float*)d_in[0];
    float* out = (float*)d_out;
    int n = in_sizes[0];

    int n4 = n / 4;
    int per_block = TPB * VPT;

    if (n4 > 0 && n4 % per_block == 0) {
        // Hot path for this problem: n4 = 9,437,184 = 9216 * 1024.
        expmlogm_copy_exact<<<n4 / per_block, TPB>>>(
            (const float4*)x, (float4*)out);
    } else if (n4 > 0) {
        int blocks = (n4 + per_block - 1) / per_block;
        expmlogm_copy_kernel<<<blocks, TPB>>>(
            (const float4*)x, (float4*)out, n4);
    }
    int tail_start = n4 * 4;
    if (n - tail_start > 0) {
        expmlogm_copy_tail<<<1, 128>>>(x, out, tail_start, n);
    }
}